// round 1
// baseline (speedup 1.0000x reference)
#include <cuda_runtime.h>
#include <math.h>

// ---------------- problem constants ----------------
#define BB 4
#define NN 1024
#define DIMD 768
#define NHEAD 12
#define DHEAD 64
#define HH 32

// ---------------- static scratch (no runtime alloc allowed) ----------------
// layout (floats):
//  ep   : 2*4*1024*1024 = 8388608
//  wmap : 4*1024*1024   = 4194304
//  lnx, lnk, lnv, q, k, v, att, p0, z0 : 9 * 4096*768 = 9*3145728
//  hid  : 4096*1536 = 6291456
// total = 47185920 floats (~189 MB)
__device__ float g_scratch[47185920];
__device__ float g_params[8][16];

static const size_t OFF_EP   = 0;
static const size_t OFF_WM   = 8388608;
static const size_t OFF_LNX  = 12582912;
static const size_t OFF_LNK  = 15728640;
static const size_t OFF_LNV  = 18874368;
static const size_t OFF_Q    = 22020096;
static const size_t OFF_K    = 25165824;
static const size_t OFF_V    = 28311552;
static const size_t OFF_ATT  = 31457280;
static const size_t OFF_P0   = 34603008;
static const size_t OFF_Z0   = 37748736;
static const size_t OFF_HID  = 40894464;

// ---------------- per-(dir,b) epipolar parameter setup ----------------
// dir 0: src=c2w[1], tgt=c2w[0]  (e1)
// dir 1: src=c2w[0], tgt=c2w[1]  (e2 before transpose)
__global__ void setup_params_kernel(const float* __restrict__ intr,
                                    const float* __restrict__ c2w) {
    int t = threadIdx.x;
    if (t >= 8) return;
    int dir = t >> 2, b = t & 3;

    float k3[3][3];
    const float Wf = 32.0f * 16.0f / 9.0f;
    for (int i = 0; i < 3; i++)
        for (int j = 0; j < 3; j++)
            k3[i][j] = intr[b * 16 + i * 4 + j];
    for (int j = 0; j < 3; j++) { k3[0][j] *= Wf; k3[1][j] *= 32.0f; }
    k3[0][2] = 16.0f; k3[1][2] = 16.0f;

    int si = (dir == 0) ? 1 : 0;
    int ti = (dir == 0) ? 0 : 1;
    const float* S = c2w + (si * 4 + b) * 16;
    const float* T = c2w + (ti * 4 + b) * 16;
    float sr[3][3], st[3], tr[3][3], tt[3];
    for (int i = 0; i < 3; i++) {
        for (int j = 0; j < 3; j++) { sr[i][j] = S[i * 4 + j]; tr[i][j] = T[i * 4 + j]; }
        st[i] = S[i * 4 + 3]; tt[i] = T[i * 4 + 3];
    }
    // inv(tr) via adjugate
    float det = tr[0][0] * (tr[1][1] * tr[2][2] - tr[1][2] * tr[2][1])
              - tr[0][1] * (tr[1][0] * tr[2][2] - tr[1][2] * tr[2][0])
              + tr[0][2] * (tr[1][0] * tr[2][1] - tr[1][1] * tr[2][0]);
    float id = 1.0f / det;
    float ti3[3][3];
    ti3[0][0] = (tr[1][1] * tr[2][2] - tr[1][2] * tr[2][1]) * id;
    ti3[0][1] = (tr[0][2] * tr[2][1] - tr[0][1] * tr[2][2]) * id;
    ti3[0][2] = (tr[0][1] * tr[1][2] - tr[0][2] * tr[1][1]) * id;
    ti3[1][0] = (tr[1][2] * tr[2][0] - tr[1][0] * tr[2][2]) * id;
    ti3[1][1] = (tr[0][0] * tr[2][2] - tr[0][2] * tr[2][0]) * id;
    ti3[1][2] = (tr[0][2] * tr[1][0] - tr[0][0] * tr[1][2]) * id;
    ti3[2][0] = (tr[1][0] * tr[2][1] - tr[1][1] * tr[2][0]) * id;
    ti3[2][1] = (tr[0][1] * tr[2][0] - tr[0][0] * tr[2][1]) * id;
    ti3[2][2] = (tr[0][0] * tr[1][1] - tr[0][1] * tr[1][0]) * id;

    float TR[3][3], M[3][3];
    for (int i = 0; i < 3; i++)
        for (int j = 0; j < 3; j++) {
            float s = 0.f;
            for (int kk2 = 0; kk2 < 3; kk2++) s += ti3[i][kk2] * sr[kk2][j];
            TR[i][j] = s;
        }
    for (int i = 0; i < 3; i++)
        for (int j = 0; j < 3; j++) {
            float s = 0.f;
            for (int kk2 = 0; kk2 < 3; kk2++) s += k3[i][kk2] * TR[kk2][j];
            M[i][j] = s;
        }
    float o2[3], tv[3];
    for (int i = 0; i < 3; i++) {
        float s = 0.f;
        for (int kk2 = 0; kk2 < 3; kk2++) s += ti3[i][kk2] * st[kk2];
        o2[i] = s - tt[i];
    }
    for (int i = 0; i < 3; i++) {
        float s = 0.f;
        for (int kk2 = 0; kk2 < 3; kk2++) s += k3[i][kk2] * o2[kk2];
        tv[i] = s;
    }
    float* P = g_params[t];
    P[0] = M[0][0]; P[1] = M[0][1]; P[2] = M[0][2];
    P[3] = M[1][0]; P[4] = M[1][1]; P[5] = M[1][2];
    P[6] = M[2][0]; P[7] = M[2][1]; P[8] = M[2][2];
    P[9] = tv[0]; P[10] = tv[1]; P[11] = tv[2];
    P[12] = k3[0][0]; P[13] = k3[1][1]; P[14] = k3[0][2]; P[15] = k3[1][2];
}

// ---------------- epipolar row kernel: one block per (i, b, dir) ----------------
__global__ void epipolar_kernel(float* __restrict__ ep) {
    int i = blockIdx.x, b = blockIdx.y, dir = blockIdx.z;
    const float* P = g_params[dir * 4 + b];
    float M0 = P[0], M1 = P[1], M2 = P[2], M3 = P[3], M4 = P[4], M5 = P[5],
          M6 = P[6], M7 = P[7], M8 = P[8];
    float tv0 = P[9], tv1 = P[10], tv2 = P[11];
    float fx = P[12], fy = P[13], cx = P[14], cy = P[15];

    float ncx = ((float)(i & 31) - cx) / fx;
    float ncy = ((float)(i >> 5) - cy) / fy;
    float pux = M0 * ncx + M1 * ncy + M2 + tv0;
    float puy = M3 * ncx + M4 * ncy + M5 + tv1;
    float puz = M6 * ncx + M7 * ncy + M8 + tv2;
    float invz = 1.0f / (puz + 1e-6f);
    float px = pux * invz, py = puy * invz, pz = puz * invz;
    float ozi = 1.0f / tv2;
    float ox = tv0 * ozi, oy = tv1 * ozi, oz = tv2 * ozi;
    float ax = px - ox, ay = py - oy, az = pz - oz;
    float vlen = sqrtf(ax * ax + ay * ay + az * az);

    int tid = threadIdx.x;
    float dwv[4];
    float lmax = -1e30f;
#pragma unroll
    for (int it = 0; it < 4; it++) {
        int j = tid + it * 256;
        float bx = (float)(j & 31) - ox;
        float by = (float)(j >> 5) - oy;
        float bz = 1.0f - oz;
        float crx = ay * bz - az * by;
        float cry = az * bx - ax * bz;
        float crz = ax * by - ay * bx;
        float area = sqrtf(crx * crx + cry * cry + crz * crz);
        float dist = area / vlen;
        float dw = 1.0f / (1.0f + expf(50.0f * (dist - 0.5f)));
        dwv[it] = dw;
        lmax = fmaxf(lmax, dw);
    }
    __shared__ float red[256];
    red[tid] = lmax;
    __syncthreads();
    for (int s = 128; s > 0; s >>= 1) {
        if (tid < s) red[tid] = fmaxf(red[tid], red[tid + s]);
        __syncthreads();
    }
    float rmax = red[0];
    float* dst = ep + ((size_t)((dir * 4 + b) * 1024 + i) << 10);
#pragma unroll
    for (int it = 0; it < 4; it++) {
        int j = tid + it * 256;
        dst[j] = (rmax < 0.5f) ? 1.0f : dwv[it];
    }
}

// ---------------- wmap = e1 * e2^T, plus 12-way head broadcast to output ----------------
__global__ void wmap_kernel(const float* __restrict__ ep,
                            float* __restrict__ wm,
                            float* __restrict__ out_wm) {
    int b = blockIdx.z;
    int I0 = blockIdx.y << 5, J0 = blockIdx.x << 5;
    int tx = threadIdx.x, ty = threadIdx.y;
    __shared__ float s1[32][33];
    const float* e0 = ep + ((size_t)(b * 1024) << 10);
    const float* e1 = ep + ((size_t)((4 + b) * 1024) << 10);
    float a = e0[(size_t)(I0 + ty) * 1024 + J0 + tx];
    s1[ty][tx] = e1[(size_t)(J0 + ty) * 1024 + I0 + tx];
    __syncthreads();
    float w = a * s1[tx][ty];
    size_t off = (size_t)(I0 + ty) * 1024 + J0 + tx;
    wm[((size_t)b << 20) + off] = w;
#pragma unroll
    for (int h = 0; h < 12; h++)
        out_wm[((size_t)(b * 12 + h) << 20) + off] = w;
}

// ---------------- layernorm (optional residual add), 768 cols ----------------
__global__ void ln_kernel(const float* __restrict__ in, const float* __restrict__ res,
                          const float* __restrict__ gam, const float* __restrict__ bet,
                          float* __restrict__ out) {
    int row = blockIdx.x;
    int tid = threadIdx.x;
    const float* p = in + (size_t)row * 768;
    float v[3];
#pragma unroll
    for (int it = 0; it < 3; it++) {
        int c = tid + it * 256;
        v[it] = p[c];
        if (res) v[it] += res[(size_t)row * 768 + c];
    }
    __shared__ float red[256];
    red[tid] = v[0] + v[1] + v[2];
    __syncthreads();
    for (int s = 128; s > 0; s >>= 1) {
        if (tid < s) red[tid] += red[tid + s];
        __syncthreads();
    }
    float mu = red[0] * (1.0f / 768.0f);
    __syncthreads();
    float d0 = v[0] - mu, d1 = v[1] - mu, d2 = v[2] - mu;
    red[tid] = d0 * d0 + d1 * d1 + d2 * d2;
    __syncthreads();
    for (int s = 128; s > 0; s >>= 1) {
        if (tid < s) red[tid] += red[tid + s];
        __syncthreads();
    }
    float var = red[0] * (1.0f / 768.0f);
    float rstd = rsqrtf(var + 1e-5f);
#pragma unroll
    for (int it = 0; it < 3; it++) {
        int c = tid + it * 256;
        out[(size_t)row * 768 + c] = (v[it] - mu) * rstd * gam[c] + bet[c];
    }
}

// ---------------- tiled SGEMM: C[M,N] = A[M,K] @ B[K,N] + bias (+gelu) ----------------
__global__ void sgemm_kernel(const float* __restrict__ A, const float* __restrict__ B,
                             const float* __restrict__ bias, float* __restrict__ C,
                             int M, int N, int K, int act) {
    __shared__ float As[16][65];
    __shared__ float Bs[16][65];
    int tx = threadIdx.x, ty = threadIdx.y;
    int tid = ty * 16 + tx;
    int m0 = blockIdx.y << 6, n0 = blockIdx.x << 6;
    float acc[4][4] = {};
    for (int k0 = 0; k0 < K; k0 += 16) {
#pragma unroll
        for (int i = 0; i < 4; i++) {
            int e = (tid << 2) + i;
            int m = e >> 4, kk = e & 15;
            As[kk][m] = A[(size_t)(m0 + m) * K + k0 + kk];
        }
#pragma unroll
        for (int i = 0; i < 4; i++) {
            int e = (tid << 2) + i;
            int kk = e >> 6, n = e & 63;
            Bs[kk][n] = B[(size_t)(k0 + kk) * N + n0 + n];
        }
        __syncthreads();
#pragma unroll
        for (int kk = 0; kk < 16; kk++) {
            float av[4], bv[4];
#pragma unroll
            for (int i = 0; i < 4; i++) av[i] = As[kk][(ty << 2) + i];
#pragma unroll
            for (int j = 0; j < 4; j++) bv[j] = Bs[kk][(tx << 2) + j];
#pragma unroll
            for (int i = 0; i < 4; i++)
#pragma unroll
                for (int j = 0; j < 4; j++) acc[i][j] += av[i] * bv[j];
        }
        __syncthreads();
    }
#pragma unroll
    for (int i = 0; i < 4; i++) {
        int m = m0 + (ty << 2) + i;
#pragma unroll
        for (int j = 0; j < 4; j++) {
            int n = n0 + (tx << 2) + j;
            float val = acc[i][j] + bias[n];
            if (act == 1) val = 0.5f * val * (1.0f + erff(val * 0.70710678118654752f));
            C[(size_t)m * N + n] = val;
        }
    }
}

// ---------------- fused attention: flash-style, 32q x 32k tiles ----------------
__global__ void attn_kernel(const float* __restrict__ q, const float* __restrict__ k,
                            const float* __restrict__ v, const float* __restrict__ wm,
                            float* __restrict__ att_out) {
    int bh = blockIdx.y;
    int b = bh / 12, h = bh - b * 12;
    int q0 = blockIdx.x << 5;
    int tid = threadIdx.x;

    __shared__ float qs[32][65];
    __shared__ float ks[32][65];
    __shared__ float vs[32][65];
    __shared__ float sc[32][33];
    __shared__ float ws[32][33];

#pragma unroll
    for (int it = 0; it < 8; it++) {
        int e = tid + (it << 8);
        int r = e >> 6, d = e & 63;
        qs[r][d] = q[(size_t)(b * 1024 + q0 + r) * 768 + h * 64 + d];
    }
    int qr = tid >> 3;
    int dg = tid & 7;
    int d0 = dg << 3;
    float acc[8] = {0, 0, 0, 0, 0, 0, 0, 0};
    float mrun = -1e30f, lrun = 0.0f;
    const float* wbase = wm + ((size_t)b << 20);

    for (int kt = 0; kt < 32; kt++) {
        int k0 = kt << 5;
        __syncthreads();
#pragma unroll
        for (int it = 0; it < 8; it++) {
            int e = tid + (it << 8);
            int r = e >> 6, d = e & 63;
            size_t g = (size_t)(b * 1024 + k0 + r) * 768 + h * 64 + d;
            ks[r][d] = k[g];
            vs[r][d] = v[g];
        }
#pragma unroll
        for (int it = 0; it < 4; it++) {
            int e = tid + (it << 8);
            int r = e >> 5, c = e & 31;
            ws[r][c] = wbase[(size_t)(q0 + r) * 1024 + k0 + c];
        }
        __syncthreads();

        float s[4] = {0, 0, 0, 0};
#pragma unroll
        for (int d = 0; d < 64; d++) {
            float qv = qs[qr][d];
#pragma unroll
            for (int jj = 0; jj < 4; jj++) s[jj] += qv * ks[(dg << 2) + jj][d];
        }
        float rm = -1e30f;
#pragma unroll
        for (int jj = 0; jj < 4; jj++) {
            s[jj] = s[jj] * 0.125f * ws[qr][(dg << 2) + jj];
            rm = fmaxf(rm, s[jj]);
        }
        rm = fmaxf(rm, __shfl_xor_sync(0xffffffffu, rm, 1));
        rm = fmaxf(rm, __shfl_xor_sync(0xffffffffu, rm, 2));
        rm = fmaxf(rm, __shfl_xor_sync(0xffffffffu, rm, 4));
        float newm = fmaxf(mrun, rm);
        float alpha = expf(mrun - newm);
        mrun = newm;
        float rs = 0.f;
#pragma unroll
        for (int jj = 0; jj < 4; jj++) {
            float pv = expf(s[jj] - newm);
            sc[qr][(dg << 2) + jj] = pv;
            rs += pv;
        }
        rs += __shfl_xor_sync(0xffffffffu, rs, 1);
        rs += __shfl_xor_sync(0xffffffffu, rs, 2);
        rs += __shfl_xor_sync(0xffffffffu, rs, 4);
        lrun = lrun * alpha + rs;
#pragma unroll
        for (int j = 0; j < 8; j++) acc[j] *= alpha;
        __syncthreads();
#pragma unroll
        for (int kc = 0; kc < 32; kc++) {
            float pv = sc[qr][kc];
#pragma unroll
            for (int j = 0; j < 8; j++) acc[j] += pv * vs[kc][d0 + j];
        }
    }
    float inv = 1.0f / lrun;
#pragma unroll
    for (int j = 0; j < 8; j++)
        att_out[(size_t)(b * 1024 + q0 + qr) * 768 + h * 64 + d0 + j] = acc[j] * inv;
}

// ---------------- launch ----------------
extern "C" void kernel_launch(void* const* d_in, const int* in_sizes, int n_in,
                              void* d_out, int out_size) {
    const float* x      = (const float*)d_in[0];
    const float* src    = (const float*)d_in[1];
    const float* intr   = (const float*)d_in[2];
    const float* c2w    = (const float*)d_in[3];
    const float* lnq_g  = (const float*)d_in[4];
    const float* lnq_b  = (const float*)d_in[5];
    const float* Wq     = (const float*)d_in[6];
    const float* bq     = (const float*)d_in[7];
    const float* lnk_g  = (const float*)d_in[8];
    const float* lnk_b  = (const float*)d_in[9];
    const float* Wk     = (const float*)d_in[10];
    const float* bk     = (const float*)d_in[11];
    const float* lnv_g  = (const float*)d_in[12];
    const float* lnv_b  = (const float*)d_in[13];
    const float* Wv     = (const float*)d_in[14];
    const float* bv     = (const float*)d_in[15];
    const float* Wp     = (const float*)d_in[16];
    const float* bp     = (const float*)d_in[17];
    const float* pre_g  = (const float*)d_in[18];
    const float* pre_b  = (const float*)d_in[19];
    const float* W1     = (const float*)d_in[20];
    const float* b1     = (const float*)d_in[21];
    const float* W2     = (const float*)d_in[22];
    const float* b2     = (const float*)d_in[23];
    const float* post_g = (const float*)d_in[24];
    const float* post_b = (const float*)d_in[25];

    float* out_z  = (float*)d_out;
    float* out_wm = out_z + (size_t)4 * 1024 * 768;

    void* sp = nullptr;
    cudaGetSymbolAddress(&sp, g_scratch);
    float* base = (float*)sp;
    float* ep  = base + OFF_EP;
    float* wm  = base + OFF_WM;
    float* lnx = base + OFF_LNX;
    float* lnk = base + OFF_LNK;
    float* lnv = base + OFF_LNV;
    float* qb  = base + OFF_Q;
    float* kb  = base + OFF_K;
    float* vb  = base + OFF_V;
    float* att = base + OFF_ATT;
    float* p0  = base + OFF_P0;
    float* z0  = base + OFF_Z0;
    float* hid = base + OFF_HID;

    setup_params_kernel<<<1, 8>>>(intr, c2w);
    epipolar_kernel<<<dim3(1024, 4, 2), 256>>>(ep);
    wmap_kernel<<<dim3(32, 32, 4), dim3(32, 32)>>>(ep, wm, out_wm);

    ln_kernel<<<4096, 256>>>(x, nullptr, lnq_g, lnq_b, lnx);
    ln_kernel<<<4096, 256>>>(src, nullptr, lnk_g, lnk_b, lnk);
    ln_kernel<<<4096, 256>>>(src, nullptr, lnv_g, lnv_b, lnv);

    sgemm_kernel<<<dim3(12, 64), dim3(16, 16)>>>(lnx, Wq, bq, qb, 4096, 768, 768, 0);
    sgemm_kernel<<<dim3(12, 64), dim3(16, 16)>>>(lnk, Wk, bk, kb, 4096, 768, 768, 0);
    sgemm_kernel<<<dim3(12, 64), dim3(16, 16)>>>(lnv, Wv, bv, vb, 4096, 768, 768, 0);

    attn_kernel<<<dim3(32, 48), 256>>>(qb, kb, vb, wm, att);

    sgemm_kernel<<<dim3(12, 64), dim3(16, 16)>>>(att, Wp, bp, p0, 4096, 768, 768, 0);
    ln_kernel<<<4096, 256>>>(p0, nullptr, pre_g, pre_b, z0);
    sgemm_kernel<<<dim3(24, 64), dim3(16, 16)>>>(z0, W1, b1, hid, 4096, 1536, 768, 1);
    sgemm_kernel<<<dim3(12, 64), dim3(16, 16)>>>(hid, W2, b2, p0, 4096, 768, 1536, 0);
    ln_kernel<<<4096, 256>>>(p0, z0, post_g, post_b, out_z);
}

// round 3
// speedup vs baseline: 1.6195x; 1.6195x over previous
#include <cuda_runtime.h>
#include <math.h>
#include <stdint.h>

// ---------------- problem constants ----------------
#define BB 4
#define NN 1024
#define DIMD 768
#define NHEAD 12
#define DHEAD 64

// ---------------- static scratch ----------------
__device__ float g_scratch[51904512];
__device__ float g_params[8][16];

static const size_t OFF_EP   = 0;
static const size_t OFF_WM   = 8388608;
static const size_t OFF_LNX  = 12582912;
static const size_t OFF_LNK  = 15728640;
static const size_t OFF_LNV  = 18874368;
static const size_t OFF_Q    = 22020096;
static const size_t OFF_K    = 25165824;
static const size_t OFF_V    = 28311552;
static const size_t OFF_ATT  = 31457280;
static const size_t OFF_P0   = 34603008;
static const size_t OFF_Z0   = 37748736;
static const size_t OFF_HID  = 40894464;
static const size_t OFF_WQT  = 47185920;
static const size_t OFF_WKT  = 47775744;
static const size_t OFF_WVT  = 48365568;
static const size_t OFF_WPT  = 48955392;
static const size_t OFF_W1T  = 49545216;
static const size_t OFF_W2T  = 50724864;

// =========================================================================
// helpers
// =========================================================================
__device__ __forceinline__ uint32_t f2tf32(float f) {
    uint32_t u;
    asm("cvt.rna.tf32.f32 %0, %1;" : "=r"(u) : "f"(f));
    return u;
}

__device__ __forceinline__ void mma_tf32(float d[4], const uint32_t a[4], const uint32_t b[2]) {
    asm volatile(
        "mma.sync.aligned.m16n8k8.row.col.f32.tf32.tf32.f32 "
        "{%0,%1,%2,%3}, {%4,%5,%6,%7}, {%8,%9}, {%0,%1,%2,%3};"
        : "+f"(d[0]), "+f"(d[1]), "+f"(d[2]), "+f"(d[3])
        : "r"(a[0]), "r"(a[1]), "r"(a[2]), "r"(a[3]), "r"(b[0]), "r"(b[1]));
}

// =========================================================================
// weight transpose: in [R][C] -> out [C][R]
// =========================================================================
__global__ void transpose_kernel(const float* __restrict__ in, float* __restrict__ out,
                                 int R, int C) {
    __shared__ float t[32][33];
    int c0 = blockIdx.x << 5, r0 = blockIdx.y << 5;
    int tx = threadIdx.x, ty = threadIdx.y;
    t[ty][tx] = in[(size_t)(r0 + ty) * C + c0 + tx];
    __syncthreads();
    out[(size_t)(c0 + ty) * R + r0 + tx] = t[tx][ty];
}

// =========================================================================
// mma.sync tf32 GEMM: C[M,N] = A[M,K] @ Bt[N,K]^T + bias (+gelu)
// 128x128 CTA tile, 8 warps (2x4), warp tile 64x32, K-step 32
// =========================================================================
__global__ __launch_bounds__(256, 1) void gemm_mma_kernel(
    const float* __restrict__ A, const float* __restrict__ Bt,
    const float* __restrict__ bias, float* __restrict__ C,
    int M, int N, int K, int act) {
    __shared__ uint32_t As[128][36];
    __shared__ uint32_t Bs[128][36];

    int tid = threadIdx.x;
    int lane = tid & 31, warp = tid >> 5;
    int wm = warp >> 2, wn = warp & 3;          // warp grid 2 x 4
    int g = lane >> 2, t4 = lane & 3;           // fragment lane decomposition
    int m0 = blockIdx.y << 7, n0 = blockIdx.x << 7;

    float acc[4][4][4];
#pragma unroll
    for (int i = 0; i < 4; i++)
#pragma unroll
        for (int j = 0; j < 4; j++)
#pragma unroll
            for (int r = 0; r < 4; r++) acc[i][j][r] = 0.f;

    const int NT = K >> 5;
    for (int kt = 0; kt < NT; kt++) {
        int kbase = kt << 5;
        // load A,B tiles: 128 rows x 32 cols each; 1024 float4 per tile, 4 per thread
#pragma unroll
        for (int it = 0; it < 4; it++) {
            int e = (it << 8) + tid;
            int row = e >> 3, q = (e & 7) << 2;
            float4 av = *(const float4*)(A + (size_t)(m0 + row) * K + kbase + q);
            As[row][q + 0] = f2tf32(av.x);
            As[row][q + 1] = f2tf32(av.y);
            As[row][q + 2] = f2tf32(av.z);
            As[row][q + 3] = f2tf32(av.w);
            float4 bv = *(const float4*)(Bt + (size_t)(n0 + row) * K + kbase + q);
            Bs[row][q + 0] = f2tf32(bv.x);
            Bs[row][q + 1] = f2tf32(bv.y);
            Bs[row][q + 2] = f2tf32(bv.z);
            Bs[row][q + 3] = f2tf32(bv.w);
        }
        __syncthreads();

#pragma unroll
        for (int kf = 0; kf < 4; kf++) {
            int kc = kf << 3;
            uint32_t af[4][4], bf[4][2];
#pragma unroll
            for (int mi = 0; mi < 4; mi++) {
                int row = (wm << 6) + (mi << 4) + g;
                af[mi][0] = As[row][kc + t4];
                af[mi][1] = As[row + 8][kc + t4];
                af[mi][2] = As[row][kc + t4 + 4];
                af[mi][3] = As[row + 8][kc + t4 + 4];
            }
#pragma unroll
            for (int ni = 0; ni < 4; ni++) {
                int nr = (wn << 5) + (ni << 3) + g;
                bf[ni][0] = Bs[nr][kc + t4];
                bf[ni][1] = Bs[nr][kc + t4 + 4];
            }
#pragma unroll
            for (int mi = 0; mi < 4; mi++)
#pragma unroll
                for (int ni = 0; ni < 4; ni++)
                    mma_tf32(acc[mi][ni], af[mi], bf[ni]);
        }
        __syncthreads();
    }

    // epilogue: direct stores with bias (+gelu)
#pragma unroll
    for (int mi = 0; mi < 4; mi++) {
        int row0 = m0 + (wm << 6) + (mi << 4) + g;
#pragma unroll
        for (int ni = 0; ni < 4; ni++) {
            int col = n0 + (wn << 5) + (ni << 3) + (t4 << 1);
            float b0 = bias[col], b1 = bias[col + 1];
#pragma unroll
            for (int half = 0; half < 2; half++) {
                int row = row0 + half * 8;
                float v0 = acc[mi][ni][half * 2 + 0] + b0;
                float v1 = acc[mi][ni][half * 2 + 1] + b1;
                if (act) {
                    v0 = 0.5f * v0 * (1.0f + erff(v0 * 0.70710678118654752f));
                    v1 = 0.5f * v1 * (1.0f + erff(v1 * 0.70710678118654752f));
                }
                float2 st = make_float2(v0, v1);
                *(float2*)(C + (size_t)row * N + col) = st;
            }
        }
    }
}

// =========================================================================
// epipolar parameter setup
// =========================================================================
__global__ void setup_params_kernel(const float* __restrict__ intr,
                                    const float* __restrict__ c2w) {
    int t = threadIdx.x;
    if (t >= 8) return;
    int dir = t >> 2, b = t & 3;

    float k3[3][3];
    const float Wf = 32.0f * 16.0f / 9.0f;
    for (int i = 0; i < 3; i++)
        for (int j = 0; j < 3; j++)
            k3[i][j] = intr[b * 16 + i * 4 + j];
    for (int j = 0; j < 3; j++) { k3[0][j] *= Wf; k3[1][j] *= 32.0f; }
    k3[0][2] = 16.0f; k3[1][2] = 16.0f;

    int si = (dir == 0) ? 1 : 0;
    int ti = (dir == 0) ? 0 : 1;
    const float* S = c2w + (si * 4 + b) * 16;
    const float* T = c2w + (ti * 4 + b) * 16;
    float sr[3][3], st[3], tr[3][3], tt[3];
    for (int i = 0; i < 3; i++) {
        for (int j = 0; j < 3; j++) { sr[i][j] = S[i * 4 + j]; tr[i][j] = T[i * 4 + j]; }
        st[i] = S[i * 4 + 3]; tt[i] = T[i * 4 + 3];
    }
    float det = tr[0][0] * (tr[1][1] * tr[2][2] - tr[1][2] * tr[2][1])
              - tr[0][1] * (tr[1][0] * tr[2][2] - tr[1][2] * tr[2][0])
              + tr[0][2] * (tr[1][0] * tr[2][1] - tr[1][1] * tr[2][0]);
    float id = 1.0f / det;
    float ti3[3][3];
    ti3[0][0] = (tr[1][1] * tr[2][2] - tr[1][2] * tr[2][1]) * id;
    ti3[0][1] = (tr[0][2] * tr[2][1] - tr[0][1] * tr[2][2]) * id;
    ti3[0][2] = (tr[0][1] * tr[1][2] - tr[0][2] * tr[1][1]) * id;
    ti3[1][0] = (tr[1][2] * tr[2][0] - tr[1][0] * tr[2][2]) * id;
    ti3[1][1] = (tr[0][0] * tr[2][2] - tr[0][2] * tr[2][0]) * id;
    ti3[1][2] = (tr[0][2] * tr[1][0] - tr[0][0] * tr[1][2]) * id;
    ti3[2][0] = (tr[1][0] * tr[2][1] - tr[1][1] * tr[2][0]) * id;
    ti3[2][1] = (tr[0][1] * tr[2][0] - tr[0][0] * tr[2][1]) * id;
    ti3[2][2] = (tr[0][0] * tr[1][1] - tr[0][1] * tr[1][0]) * id;

    float TR[3][3], Mm[3][3];
    for (int i = 0; i < 3; i++)
        for (int j = 0; j < 3; j++) {
            float s = 0.f;
            for (int kk = 0; kk < 3; kk++) s += ti3[i][kk] * sr[kk][j];
            TR[i][j] = s;
        }
    for (int i = 0; i < 3; i++)
        for (int j = 0; j < 3; j++) {
            float s = 0.f;
            for (int kk = 0; kk < 3; kk++) s += k3[i][kk] * TR[kk][j];
            Mm[i][j] = s;
        }
    float o2[3], tv[3];
    for (int i = 0; i < 3; i++) {
        float s = 0.f;
        for (int kk = 0; kk < 3; kk++) s += ti3[i][kk] * st[kk];
        o2[i] = s - tt[i];
    }
    for (int i = 0; i < 3; i++) {
        float s = 0.f;
        for (int kk = 0; kk < 3; kk++) s += k3[i][kk] * o2[kk];
        tv[i] = s;
    }
    float* P = g_params[t];
    P[0] = Mm[0][0]; P[1] = Mm[0][1]; P[2] = Mm[0][2];
    P[3] = Mm[1][0]; P[4] = Mm[1][1]; P[5] = Mm[1][2];
    P[6] = Mm[2][0]; P[7] = Mm[2][1]; P[8] = Mm[2][2];
    P[9] = tv[0]; P[10] = tv[1]; P[11] = tv[2];
    P[12] = k3[0][0]; P[13] = k3[1][1]; P[14] = k3[0][2]; P[15] = k3[1][2];
}

// =========================================================================
// epipolar rows
// =========================================================================
__global__ void epipolar_kernel(float* __restrict__ ep) {
    int i = blockIdx.x, b = blockIdx.y, dir = blockIdx.z;
    const float* P = g_params[dir * 4 + b];
    float M0 = P[0], M1 = P[1], M2 = P[2], M3 = P[3], M4 = P[4], M5 = P[5],
          M6 = P[6], M7 = P[7], M8 = P[8];
    float tv0 = P[9], tv1 = P[10], tv2 = P[11];
    float fx = P[12], fy = P[13], cx = P[14], cy = P[15];

    float ncx = ((float)(i & 31) - cx) / fx;
    float ncy = ((float)(i >> 5) - cy) / fy;
    float pux = M0 * ncx + M1 * ncy + M2 + tv0;
    float puy = M3 * ncx + M4 * ncy + M5 + tv1;
    float puz = M6 * ncx + M7 * ncy + M8 + tv2;
    float invz = 1.0f / (puz + 1e-6f);
    float px = pux * invz, py = puy * invz, pz = puz * invz;
    float ozi = 1.0f / tv2;
    float ox = tv0 * ozi, oy = tv1 * ozi, oz = tv2 * ozi;
    float ax = px - ox, ay = py - oy, az = pz - oz;
    float vlen = sqrtf(ax * ax + ay * ay + az * az);

    int tid = threadIdx.x;
    float dwv[4];
    float lmax = -1e30f;
#pragma unroll
    for (int it = 0; it < 4; it++) {
        int j = tid + it * 256;
        float bx = (float)(j & 31) - ox;
        float by = (float)(j >> 5) - oy;
        float bz = 1.0f - oz;
        float crx = ay * bz - az * by;
        float cry = az * bx - ax * bz;
        float crz = ax * by - ay * bx;
        float area = sqrtf(crx * crx + cry * cry + crz * crz);
        float dist = area / vlen;
        float dw = 1.0f / (1.0f + expf(50.0f * (dist - 0.5f)));
        dwv[it] = dw;
        lmax = fmaxf(lmax, dw);
    }
    __shared__ float red[256];
    red[tid] = lmax;
    __syncthreads();
    for (int s = 128; s > 0; s >>= 1) {
        if (tid < s) red[tid] = fmaxf(red[tid], red[tid + s]);
        __syncthreads();
    }
    float rmax = red[0];
    float* dst = ep + ((size_t)((dir * 4 + b) * 1024 + i) << 10);
#pragma unroll
    for (int it = 0; it < 4; it++) {
        int j = tid + it * 256;
        dst[j] = (rmax < 0.5f) ? 1.0f : dwv[it];
    }
}

// =========================================================================
// wmap = e1 * e2^T, plus 12-way head broadcast to output
// =========================================================================
__global__ void wmap_kernel(const float* __restrict__ ep,
                            float* __restrict__ wm,
                            float* __restrict__ out_wm) {
    int b = blockIdx.z;
    int I0 = blockIdx.y << 5, J0 = blockIdx.x << 5;
    int tx = threadIdx.x, ty = threadIdx.y;
    __shared__ float s1[32][33];
    const float* e0 = ep + ((size_t)(b * 1024) << 10);
    const float* e1 = ep + ((size_t)((4 + b) * 1024) << 10);
    float a = e0[(size_t)(I0 + ty) * 1024 + J0 + tx];
    s1[ty][tx] = e1[(size_t)(J0 + ty) * 1024 + I0 + tx];
    __syncthreads();
    float w = a * s1[tx][ty];
    size_t off = (size_t)(I0 + ty) * 1024 + J0 + tx;
    wm[((size_t)b << 20) + off] = w;
#pragma unroll
    for (int h = 0; h < 12; h++)
        out_wm[((size_t)(b * 12 + h) << 20) + off] = w;
}

// =========================================================================
// layernorm (optional residual add), 768 cols
// =========================================================================
__global__ void ln_kernel(const float* __restrict__ in, const float* __restrict__ res,
                          const float* __restrict__ gam, const float* __restrict__ bet,
                          float* __restrict__ out) {
    int row = blockIdx.x;
    int tid = threadIdx.x;
    const float* p = in + (size_t)row * 768;
    float v[3];
#pragma unroll
    for (int it = 0; it < 3; it++) {
        int c = tid + it * 256;
        v[it] = p[c];
        if (res) v[it] += res[(size_t)row * 768 + c];
    }
    __shared__ float red[256];
    red[tid] = v[0] + v[1] + v[2];
    __syncthreads();
    for (int s = 128; s > 0; s >>= 1) {
        if (tid < s) red[tid] += red[tid + s];
        __syncthreads();
    }
    float mu = red[0] * (1.0f / 768.0f);
    __syncthreads();
    float d0 = v[0] - mu, d1 = v[1] - mu, d2 = v[2] - mu;
    red[tid] = d0 * d0 + d1 * d1 + d2 * d2;
    __syncthreads();
    for (int s = 128; s > 0; s >>= 1) {
        if (tid < s) red[tid] += red[tid + s];
        __syncthreads();
    }
    float var = red[0] * (1.0f / 768.0f);
    float rstd = rsqrtf(var + 1e-5f);
#pragma unroll
    for (int it = 0; it < 3; it++) {
        int c = tid + it * 256;
        out[(size_t)row * 768 + c] = (v[it] - mu) * rstd * gam[c] + bet[c];
    }
}

// =========================================================================
// fused attention (SIMT, unchanged this round)
// =========================================================================
__global__ void attn_kernel(const float* __restrict__ q, const float* __restrict__ k,
                            const float* __restrict__ v, const float* __restrict__ wm,
                            float* __restrict__ att_out) {
    int bh = blockIdx.y;
    int b = bh / 12, h = bh - b * 12;
    int q0 = blockIdx.x << 5;
    int tid = threadIdx.x;

    __shared__ float qs[32][65];
    __shared__ float ks[32][65];
    __shared__ float vs[32][65];
    __shared__ float sc[32][33];
    __shared__ float ws[32][33];

#pragma unroll
    for (int it = 0; it < 8; it++) {
        int e = tid + (it << 8);
        int r = e >> 6, d = e & 63;
        qs[r][d] = q[(size_t)(b * 1024 + q0 + r) * 768 + h * 64 + d];
    }
    int qr = tid >> 3;
    int dg = tid & 7;
    int d0 = dg << 3;
    float acc[8] = {0, 0, 0, 0, 0, 0, 0, 0};
    float mrun = -1e30f, lrun = 0.0f;
    const float* wbase = wm + ((size_t)b << 20);

    for (int kt = 0; kt < 32; kt++) {
        int k0 = kt << 5;
        __syncthreads();
#pragma unroll
        for (int it = 0; it < 8; it++) {
            int e = tid + (it << 8);
            int r = e >> 6, d = e & 63;
            size_t g = (size_t)(b * 1024 + k0 + r) * 768 + h * 64 + d;
            ks[r][d] = k[g];
            vs[r][d] = v[g];
        }
#pragma unroll
        for (int it = 0; it < 4; it++) {
            int e = tid + (it << 8);
            int r = e >> 5, c = e & 31;
            ws[r][c] = wbase[(size_t)(q0 + r) * 1024 + k0 + c];
        }
        __syncthreads();

        float s[4] = {0, 0, 0, 0};
#pragma unroll
        for (int d = 0; d < 64; d++) {
            float qv = qs[qr][d];
#pragma unroll
            for (int jj = 0; jj < 4; jj++) s[jj] += qv * ks[(dg << 2) + jj][d];
        }
        float rm = -1e30f;
#pragma unroll
        for (int jj = 0; jj < 4; jj++) {
            s[jj] = s[jj] * 0.125f * ws[qr][(dg << 2) + jj];
            rm = fmaxf(rm, s[jj]);
        }
        rm = fmaxf(rm, __shfl_xor_sync(0xffffffffu, rm, 1));
        rm = fmaxf(rm, __shfl_xor_sync(0xffffffffu, rm, 2));
        rm = fmaxf(rm, __shfl_xor_sync(0xffffffffu, rm, 4));
        float newm = fmaxf(mrun, rm);
        float alpha = expf(mrun - newm);
        mrun = newm;
        float rs = 0.f;
#pragma unroll
        for (int jj = 0; jj < 4; jj++) {
            float pv = expf(s[jj] - newm);
            sc[qr][(dg << 2) + jj] = pv;
            rs += pv;
        }
        rs += __shfl_xor_sync(0xffffffffu, rs, 1);
        rs += __shfl_xor_sync(0xffffffffu, rs, 2);
        rs += __shfl_xor_sync(0xffffffffu, rs, 4);
        lrun = lrun * alpha + rs;
#pragma unroll
        for (int j = 0; j < 8; j++) acc[j] *= alpha;
        __syncthreads();
#pragma unroll
        for (int kc = 0; kc < 32; kc++) {
            float pv = sc[qr][kc];
#pragma unroll
            for (int j = 0; j < 8; j++) acc[j] += pv * vs[kc][d0 + j];
        }
    }
    float inv = 1.0f / lrun;
#pragma unroll
    for (int j = 0; j < 8; j++)
        att_out[(size_t)(b * 1024 + q0 + qr) * 768 + h * 64 + d0 + j] = acc[j] * inv;
}

// =========================================================================
// launch
// =========================================================================
extern "C" void kernel_launch(void* const* d_in, const int* in_sizes, int n_in,
                              void* d_out, int out_size) {
    const float* x      = (const float*)d_in[0];
    const float* src    = (const float*)d_in[1];
    const float* intr   = (const float*)d_in[2];
    const float* c2w    = (const float*)d_in[3];
    const float* lnq_g  = (const float*)d_in[4];
    const float* lnq_b  = (const float*)d_in[5];
    const float* Wq     = (const float*)d_in[6];
    const float* bq     = (const float*)d_in[7];
    const float* lnk_g  = (const float*)d_in[8];
    const float* lnk_b  = (const float*)d_in[9];
    const float* Wk     = (const float*)d_in[10];
    const float* bk     = (const float*)d_in[11];
    const float* lnv_g  = (const float*)d_in[12];
    const float* lnv_b  = (const float*)d_in[13];
    const float* Wv     = (const float*)d_in[14];
    const float* bv     = (const float*)d_in[15];
    const float* Wp     = (const float*)d_in[16];
    const float* bp     = (const float*)d_in[17];
    const float* pre_g  = (const float*)d_in[18];
    const float* pre_b  = (const float*)d_in[19];
    const float* W1     = (const float*)d_in[20];
    const float* b1     = (const float*)d_in[21];
    const float* W2     = (const float*)d_in[22];
    const float* b2     = (const float*)d_in[23];
    const float* post_g = (const float*)d_in[24];
    const float* post_b = (const float*)d_in[25];

    float* out_z  = (float*)d_out;
    float* out_wm = out_z + (size_t)4 * 1024 * 768;

    void* sp = nullptr;
    cudaGetSymbolAddress(&sp, g_scratch);
    float* base = (float*)sp;
    float* ep  = base + OFF_EP;
    float* wm  = base + OFF_WM;
    float* lnx = base + OFF_LNX;
    float* lnk = base + OFF_LNK;
    float* lnv = base + OFF_LNV;
    float* qb  = base + OFF_Q;
    float* kb  = base + OFF_K;
    float* vb  = base + OFF_V;
    float* att = base + OFF_ATT;
    float* p0  = base + OFF_P0;
    float* z0  = base + OFF_Z0;
    float* hid = base + OFF_HID;
    float* wqt = base + OFF_WQT;
    float* wkt = base + OFF_WKT;
    float* wvt = base + OFF_WVT;
    float* wpt = base + OFF_WPT;
    float* w1t = base + OFF_W1T;
    float* w2t = base + OFF_W2T;

    dim3 tb(32, 32);
    transpose_kernel<<<dim3(24, 24), tb>>>(Wq, wqt, 768, 768);
    transpose_kernel<<<dim3(24, 24), tb>>>(Wk, wkt, 768, 768);
    transpose_kernel<<<dim3(24, 24), tb>>>(Wv, wvt, 768, 768);
    transpose_kernel<<<dim3(24, 24), tb>>>(Wp, wpt, 768, 768);
    transpose_kernel<<<dim3(48, 24), tb>>>(W1, w1t, 768, 1536);
    transpose_kernel<<<dim3(24, 48), tb>>>(W2, w2t, 1536, 768);

    setup_params_kernel<<<1, 8>>>(intr, c2w);
    epipolar_kernel<<<dim3(1024, 4, 2), 256>>>(ep);
    wmap_kernel<<<dim3(32, 32, 4), dim3(32, 32)>>>(ep, wm, out_wm);

    ln_kernel<<<4096, 256>>>(x, nullptr, lnq_g, lnq_b, lnx);
    ln_kernel<<<4096, 256>>>(src, nullptr, lnk_g, lnk_b, lnk);
    ln_kernel<<<4096, 256>>>(src, nullptr, lnv_g, lnv_b, lnv);

    gemm_mma_kernel<<<dim3(6, 32), 256>>>(lnx, wqt, bq, qb, 4096, 768, 768, 0);
    gemm_mma_kernel<<<dim3(6, 32), 256>>>(lnk, wkt, bk, kb, 4096, 768, 768, 0);
    gemm_mma_kernel<<<dim3(6, 32), 256>>>(lnv, wvt, bv, vb, 4096, 768, 768, 0);

    attn_kernel<<<dim3(32, 48), 256>>>(qb, kb, vb, wm, att);

    gemm_mma_kernel<<<dim3(6, 32), 256>>>(att, wpt, bp, p0, 4096, 768, 768, 0);
    ln_kernel<<<4096, 256>>>(p0, nullptr, pre_g, pre_b, z0);
    gemm_mma_kernel<<<dim3(12, 32), 256>>>(z0, w1t, b1, hid, 4096, 1536, 768, 1);
    gemm_mma_kernel<<<dim3(6, 32), 256>>>(hid, w2t, b2, p0, 4096, 768, 1536, 0);
    ln_kernel<<<4096, 256>>>(p0, z0, post_g, post_b, out_z);
}

// round 4
// speedup vs baseline: 4.2378x; 2.6167x over previous
#include <cuda_runtime.h>
#include <math.h>
#include <stdint.h>

// ---------------- problem constants ----------------
#define BB 4
#define NN 1024
#define DIMD 768
#define NHEAD 12
#define DHEAD 64

// ---------------- static scratch ----------------
__device__ float g_scratch[51904512];
__device__ float g_params[8][16];

static const size_t OFF_EP   = 0;
static const size_t OFF_WM   = 8388608;
static const size_t OFF_LNX  = 12582912;
static const size_t OFF_LNK  = 15728640;
static const size_t OFF_LNV  = 18874368;
static const size_t OFF_Q    = 22020096;
static const size_t OFF_K    = 25165824;
static const size_t OFF_V    = 28311552;
static const size_t OFF_ATT  = 31457280;
static const size_t OFF_P0   = 34603008;
static const size_t OFF_Z0   = 37748736;
static const size_t OFF_HID  = 40894464;
static const size_t OFF_WQT  = 47185920;
static const size_t OFF_WKT  = 47775744;
static const size_t OFF_WVT  = 48365568;
static const size_t OFF_WPT  = 48955392;
static const size_t OFF_W1T  = 49545216;
static const size_t OFF_W2T  = 50724864;

// =========================================================================
// helpers
// =========================================================================
__device__ __forceinline__ uint32_t f2tf32(float f) {
    uint32_t u;
    asm("cvt.rna.tf32.f32 %0, %1;" : "=r"(u) : "f"(f));
    return u;
}

__device__ __forceinline__ void mma_tf32(float d[4], const uint32_t a[4], const uint32_t b[2]) {
    asm volatile(
        "mma.sync.aligned.m16n8k8.row.col.f32.tf32.tf32.f32 "
        "{%0,%1,%2,%3}, {%4,%5,%6,%7}, {%8,%9}, {%0,%1,%2,%3};"
        : "+f"(d[0]), "+f"(d[1]), "+f"(d[2]), "+f"(d[3])
        : "r"(a[0]), "r"(a[1]), "r"(a[2]), "r"(a[3]), "r"(b[0]), "r"(b[1]));
}

// =========================================================================
// weight transpose: in [R][C] -> out [C][R]
// =========================================================================
__global__ void transpose_kernel(const float* __restrict__ in, float* __restrict__ out,
                                 int R, int C) {
    __shared__ float t[32][33];
    int c0 = blockIdx.x << 5, r0 = blockIdx.y << 5;
    int tx = threadIdx.x, ty = threadIdx.y;
    t[ty][tx] = in[(size_t)(r0 + ty) * C + c0 + tx];
    __syncthreads();
    out[(size_t)(c0 + ty) * R + r0 + tx] = t[tx][ty];
}

// =========================================================================
// mma.sync tf32 GEMM with register prefetch
// 128x128 CTA tile, 8 warps (2x4), warp tile 64x32, K-step 32
// =========================================================================
__global__ __launch_bounds__(256) void gemm_mma_kernel(
    const float* __restrict__ A, const float* __restrict__ Bt,
    const float* __restrict__ bias, float* __restrict__ C,
    int M, int N, int K, int act) {
    __shared__ uint32_t As[128][36];
    __shared__ uint32_t Bs[128][36];

    int tid = threadIdx.x;
    int lane = tid & 31, warp = tid >> 5;
    int wm = warp >> 2, wn = warp & 3;
    int g = lane >> 2, t4 = lane & 3;
    int m0 = blockIdx.y << 7, n0 = blockIdx.x << 7;

    float acc[4][4][4];
#pragma unroll
    for (int i = 0; i < 4; i++)
#pragma unroll
        for (int j = 0; j < 4; j++)
#pragma unroll
            for (int r = 0; r < 4; r++) acc[i][j][r] = 0.f;

    // per-thread load coords: 4 (row, q) pairs
    int rowL[4], qL[4];
#pragma unroll
    for (int it = 0; it < 4; it++) {
        int e = (it << 8) + tid;
        rowL[it] = e >> 3;
        qL[it] = (e & 7) << 2;
    }

    float4 ra[4], rb[4];
    // preload kt = 0
#pragma unroll
    for (int it = 0; it < 4; it++) {
        ra[it] = *(const float4*)(A + (size_t)(m0 + rowL[it]) * K + qL[it]);
        rb[it] = *(const float4*)(Bt + (size_t)(n0 + rowL[it]) * K + qL[it]);
    }

    const int NT = K >> 5;
    for (int kt = 0; kt < NT; kt++) {
        // store current regs -> smem (tf32 convert)
#pragma unroll
        for (int it = 0; it < 4; it++) {
            int row = rowL[it], q = qL[it];
            As[row][q + 0] = f2tf32(ra[it].x);
            As[row][q + 1] = f2tf32(ra[it].y);
            As[row][q + 2] = f2tf32(ra[it].z);
            As[row][q + 3] = f2tf32(ra[it].w);
            Bs[row][q + 0] = f2tf32(rb[it].x);
            Bs[row][q + 1] = f2tf32(rb[it].y);
            Bs[row][q + 2] = f2tf32(rb[it].z);
            Bs[row][q + 3] = f2tf32(rb[it].w);
        }
        __syncthreads();

        // prefetch next tile (latency hidden behind MMA below)
        if (kt + 1 < NT) {
            int kbase = (kt + 1) << 5;
#pragma unroll
            for (int it = 0; it < 4; it++) {
                ra[it] = *(const float4*)(A + (size_t)(m0 + rowL[it]) * K + kbase + qL[it]);
                rb[it] = *(const float4*)(Bt + (size_t)(n0 + rowL[it]) * K + kbase + qL[it]);
            }
        }

#pragma unroll
        for (int kf = 0; kf < 4; kf++) {
            int kc = kf << 3;
            uint32_t af[4][4], bf[4][2];
#pragma unroll
            for (int mi = 0; mi < 4; mi++) {
                int row = (wm << 6) + (mi << 4) + g;
                af[mi][0] = As[row][kc + t4];
                af[mi][1] = As[row + 8][kc + t4];
                af[mi][2] = As[row][kc + t4 + 4];
                af[mi][3] = As[row + 8][kc + t4 + 4];
            }
#pragma unroll
            for (int ni = 0; ni < 4; ni++) {
                int nr = (wn << 5) + (ni << 3) + g;
                bf[ni][0] = Bs[nr][kc + t4];
                bf[ni][1] = Bs[nr][kc + t4 + 4];
            }
#pragma unroll
            for (int mi = 0; mi < 4; mi++)
#pragma unroll
                for (int ni = 0; ni < 4; ni++)
                    mma_tf32(acc[mi][ni], af[mi], bf[ni]);
        }
        __syncthreads();
    }

#pragma unroll
    for (int mi = 0; mi < 4; mi++) {
        int row0 = m0 + (wm << 6) + (mi << 4) + g;
#pragma unroll
        for (int ni = 0; ni < 4; ni++) {
            int col = n0 + (wn << 5) + (ni << 3) + (t4 << 1);
            float b0 = bias[col], b1 = bias[col + 1];
#pragma unroll
            for (int half = 0; half < 2; half++) {
                int row = row0 + half * 8;
                float v0 = acc[mi][ni][half * 2 + 0] + b0;
                float v1 = acc[mi][ni][half * 2 + 1] + b1;
                if (act) {
                    v0 = 0.5f * v0 * (1.0f + erff(v0 * 0.70710678118654752f));
                    v1 = 0.5f * v1 * (1.0f + erff(v1 * 0.70710678118654752f));
                }
                float2 st = make_float2(v0, v1);
                *(float2*)(C + (size_t)row * N + col) = st;
            }
        }
    }
}

// =========================================================================
// mma.sync flash attention: 128 q-rows per CTA, 64-key tiles
// dynamic smem layout (u32 offsets):
//   Qs [128][68] @ 0        (tf32, pre-scaled by 0.125)
//   Ks [64][68]  @ 8704
//   VTs[64][68]  @ 13056    (V transposed: [d][kn])
//   Ws [128][66] @ 17408    (fp32 wmap tile)
//   Ps [128][68] @ 25856    (tf32 probabilities)
// total 34560 u32 = 138240 B
// =========================================================================
__global__ __launch_bounds__(256) void attn_mma_kernel(
    const float* __restrict__ q, const float* __restrict__ k,
    const float* __restrict__ v, const float* __restrict__ wm,
    float* __restrict__ att_out) {
    extern __shared__ uint32_t dynsm[];
    uint32_t (*Qs)[68]  = (uint32_t(*)[68])(dynsm);
    uint32_t (*Ks)[68]  = (uint32_t(*)[68])(dynsm + 8704);
    uint32_t (*VTs)[68] = (uint32_t(*)[68])(dynsm + 13056);
    float    (*Ws)[66]  = (float(*)[66])(dynsm + 17408);
    uint32_t (*Ps)[68]  = (uint32_t(*)[68])(dynsm + 25856);

    int bh = blockIdx.y;
    int b = bh / 12, h = bh - b * 12;
    int q0 = blockIdx.x << 7;
    int tid = threadIdx.x;
    int lane = tid & 31, warp = tid >> 5;
    int g = lane >> 2, t4 = lane & 3;
    int r = (warp << 4) + g;

    // load Q tile (128 x 64), scale folded in
#pragma unroll
    for (int it = 0; it < 8; it++) {
        int e = (it << 8) + tid;
        int row = e >> 4, c4 = (e & 15) << 2;
        float4 qv = *(const float4*)(q + (size_t)(b * 1024 + q0 + row) * 768 + h * 64 + c4);
        Qs[row][c4 + 0] = f2tf32(qv.x * 0.125f);
        Qs[row][c4 + 1] = f2tf32(qv.y * 0.125f);
        Qs[row][c4 + 2] = f2tf32(qv.z * 0.125f);
        Qs[row][c4 + 3] = f2tf32(qv.w * 0.125f);
    }

    float of[8][4];
#pragma unroll
    for (int ni = 0; ni < 8; ni++)
#pragma unroll
        for (int j = 0; j < 4; j++) of[ni][j] = 0.f;
    float mrun_a = -1e30f, mrun_b = -1e30f, lrun_a = 0.f, lrun_b = 0.f;

    const float* wbase = wm + ((size_t)b << 20);

    for (int kt = 0; kt < 16; kt++) {
        int k0 = kt << 6;
        __syncthreads();  // protect smem from previous iteration's readers

        // load K, V (transposed), W tiles
#pragma unroll
        for (int it = 0; it < 4; it++) {
            int e = (it << 8) + tid;
            int row = e >> 4, c4 = (e & 15) << 2;
            size_t gaddr = (size_t)(b * 1024 + k0 + row) * 768 + h * 64 + c4;
            float4 kv = *(const float4*)(k + gaddr);
            Ks[row][c4 + 0] = f2tf32(kv.x);
            Ks[row][c4 + 1] = f2tf32(kv.y);
            Ks[row][c4 + 2] = f2tf32(kv.z);
            Ks[row][c4 + 3] = f2tf32(kv.w);
            float4 vv = *(const float4*)(v + gaddr);
            VTs[c4 + 0][row] = f2tf32(vv.x);
            VTs[c4 + 1][row] = f2tf32(vv.y);
            VTs[c4 + 2][row] = f2tf32(vv.z);
            VTs[c4 + 3][row] = f2tf32(vv.w);
        }
#pragma unroll
        for (int it = 0; it < 8; it++) {
            int e = (it << 8) + tid;
            int row = e >> 4, c4 = (e & 15) << 2;
            float4 wv = *(const float4*)(wbase + (size_t)(q0 + row) * 1024 + k0 + c4);
            Ws[row][c4 + 0] = wv.x;
            Ws[row][c4 + 1] = wv.y;
            Ws[row][c4 + 2] = wv.z;
            Ws[row][c4 + 3] = wv.w;
        }
        __syncthreads();

        // S = Q @ K^T  (warp: rows r..r+15, cols 0..63)
        float sacc[8][4];
#pragma unroll
        for (int ni = 0; ni < 8; ni++)
#pragma unroll
            for (int j = 0; j < 4; j++) sacc[ni][j] = 0.f;
#pragma unroll
        for (int kf = 0; kf < 8; kf++) {
            int kc = kf << 3;
            uint32_t A[4];
            A[0] = Qs[r][kc + t4];
            A[1] = Qs[r + 8][kc + t4];
            A[2] = Qs[r][kc + t4 + 4];
            A[3] = Qs[r + 8][kc + t4 + 4];
#pragma unroll
            for (int ni = 0; ni < 8; ni++) {
                uint32_t B[2];
                B[0] = Ks[(ni << 3) + g][kc + t4];
                B[1] = Ks[(ni << 3) + g][kc + t4 + 4];
                mma_tf32(sacc[ni], A, B);
            }
        }

        // apply wmap, online softmax
        float sv[8][4];
        float m_a = -1e30f, m_b = -1e30f;
#pragma unroll
        for (int ni = 0; ni < 8; ni++) {
            int c0 = (ni << 3) + (t4 << 1);
            sv[ni][0] = sacc[ni][0] * Ws[r][c0];
            sv[ni][1] = sacc[ni][1] * Ws[r][c0 + 1];
            sv[ni][2] = sacc[ni][2] * Ws[r + 8][c0];
            sv[ni][3] = sacc[ni][3] * Ws[r + 8][c0 + 1];
            m_a = fmaxf(m_a, fmaxf(sv[ni][0], sv[ni][1]));
            m_b = fmaxf(m_b, fmaxf(sv[ni][2], sv[ni][3]));
        }
        m_a = fmaxf(m_a, __shfl_xor_sync(0xffffffffu, m_a, 1));
        m_a = fmaxf(m_a, __shfl_xor_sync(0xffffffffu, m_a, 2));
        m_b = fmaxf(m_b, __shfl_xor_sync(0xffffffffu, m_b, 1));
        m_b = fmaxf(m_b, __shfl_xor_sync(0xffffffffu, m_b, 2));

        float newm_a = fmaxf(mrun_a, m_a);
        float newm_b = fmaxf(mrun_b, m_b);
        float alpha_a = expf(mrun_a - newm_a);
        float alpha_b = expf(mrun_b - newm_b);
        mrun_a = newm_a;
        mrun_b = newm_b;

        float sum_a = 0.f, sum_b = 0.f;
#pragma unroll
        for (int ni = 0; ni < 8; ni++) {
            int c0 = (ni << 3) + (t4 << 1);
            float p0 = expf(sv[ni][0] - newm_a);
            float p1 = expf(sv[ni][1] - newm_a);
            float p2 = expf(sv[ni][2] - newm_b);
            float p3 = expf(sv[ni][3] - newm_b);
            sum_a += p0 + p1;
            sum_b += p2 + p3;
            Ps[r][c0] = f2tf32(p0);
            Ps[r][c0 + 1] = f2tf32(p1);
            Ps[r + 8][c0] = f2tf32(p2);
            Ps[r + 8][c0 + 1] = f2tf32(p3);
        }
        sum_a += __shfl_xor_sync(0xffffffffu, sum_a, 1);
        sum_a += __shfl_xor_sync(0xffffffffu, sum_a, 2);
        sum_b += __shfl_xor_sync(0xffffffffu, sum_b, 1);
        sum_b += __shfl_xor_sync(0xffffffffu, sum_b, 2);
        lrun_a = lrun_a * alpha_a + sum_a;
        lrun_b = lrun_b * alpha_b + sum_b;

#pragma unroll
        for (int ni = 0; ni < 8; ni++) {
            of[ni][0] *= alpha_a;
            of[ni][1] *= alpha_a;
            of[ni][2] *= alpha_b;
            of[ni][3] *= alpha_b;
        }
        __syncthreads();  // Ps visible to all warps (each warp reads only its own rows, but keep safe ordering vs next-iter loads)

        // O += P @ V  (A = Ps rows, B = VTs [d][kn])
#pragma unroll
        for (int kf = 0; kf < 8; kf++) {
            int kc = kf << 3;
            uint32_t A[4];
            A[0] = Ps[r][kc + t4];
            A[1] = Ps[r + 8][kc + t4];
            A[2] = Ps[r][kc + t4 + 4];
            A[3] = Ps[r + 8][kc + t4 + 4];
#pragma unroll
            for (int ni = 0; ni < 8; ni++) {
                uint32_t B[2];
                B[0] = VTs[(ni << 3) + g][kc + t4];
                B[1] = VTs[(ni << 3) + g][kc + t4 + 4];
                mma_tf32(of[ni], A, B);
            }
        }
    }

    float ia = 1.0f / lrun_a, ib = 1.0f / lrun_b;
#pragma unroll
    for (int ni = 0; ni < 8; ni++) {
        int col = h * 64 + (ni << 3) + (t4 << 1);
        float2 oa = make_float2(of[ni][0] * ia, of[ni][1] * ia);
        float2 ob = make_float2(of[ni][2] * ib, of[ni][3] * ib);
        *(float2*)(att_out + (size_t)(b * 1024 + q0 + r) * 768 + col) = oa;
        *(float2*)(att_out + (size_t)(b * 1024 + q0 + r + 8) * 768 + col) = ob;
    }
}

// =========================================================================
// epipolar parameter setup
// =========================================================================
__global__ void setup_params_kernel(const float* __restrict__ intr,
                                    const float* __restrict__ c2w) {
    int t = threadIdx.x;
    if (t >= 8) return;
    int dir = t >> 2, b = t & 3;

    float k3[3][3];
    const float Wf = 32.0f * 16.0f / 9.0f;
    for (int i = 0; i < 3; i++)
        for (int j = 0; j < 3; j++)
            k3[i][j] = intr[b * 16 + i * 4 + j];
    for (int j = 0; j < 3; j++) { k3[0][j] *= Wf; k3[1][j] *= 32.0f; }
    k3[0][2] = 16.0f; k3[1][2] = 16.0f;

    int si = (dir == 0) ? 1 : 0;
    int ti = (dir == 0) ? 0 : 1;
    const float* S = c2w + (si * 4 + b) * 16;
    const float* T = c2w + (ti * 4 + b) * 16;
    float sr[3][3], st[3], tr[3][3], tt[3];
    for (int i = 0; i < 3; i++) {
        for (int j = 0; j < 3; j++) { sr[i][j] = S[i * 4 + j]; tr[i][j] = T[i * 4 + j]; }
        st[i] = S[i * 4 + 3]; tt[i] = T[i * 4 + 3];
    }
    float det = tr[0][0] * (tr[1][1] * tr[2][2] - tr[1][2] * tr[2][1])
              - tr[0][1] * (tr[1][0] * tr[2][2] - tr[1][2] * tr[2][0])
              + tr[0][2] * (tr[1][0] * tr[2][1] - tr[1][1] * tr[2][0]);
    float id = 1.0f / det;
    float ti3[3][3];
    ti3[0][0] = (tr[1][1] * tr[2][2] - tr[1][2] * tr[2][1]) * id;
    ti3[0][1] = (tr[0][2] * tr[2][1] - tr[0][1] * tr[2][2]) * id;
    ti3[0][2] = (tr[0][1] * tr[1][2] - tr[0][2] * tr[1][1]) * id;
    ti3[1][0] = (tr[1][2] * tr[2][0] - tr[1][0] * tr[2][2]) * id;
    ti3[1][1] = (tr[0][0] * tr[2][2] - tr[0][2] * tr[2][0]) * id;
    ti3[1][2] = (tr[0][2] * tr[1][0] - tr[0][0] * tr[1][2]) * id;
    ti3[2][0] = (tr[1][0] * tr[2][1] - tr[1][1] * tr[2][0]) * id;
    ti3[2][1] = (tr[0][1] * tr[2][0] - tr[0][0] * tr[2][1]) * id;
    ti3[2][2] = (tr[0][0] * tr[1][1] - tr[0][1] * tr[1][0]) * id;

    float TR[3][3], Mm[3][3];
    for (int i = 0; i < 3; i++)
        for (int j = 0; j < 3; j++) {
            float s = 0.f;
            for (int kk = 0; kk < 3; kk++) s += ti3[i][kk] * sr[kk][j];
            TR[i][j] = s;
        }
    for (int i = 0; i < 3; i++)
        for (int j = 0; j < 3; j++) {
            float s = 0.f;
            for (int kk = 0; kk < 3; kk++) s += k3[i][kk] * TR[kk][j];
            Mm[i][j] = s;
        }
    float o2[3], tv[3];
    for (int i = 0; i < 3; i++) {
        float s = 0.f;
        for (int kk = 0; kk < 3; kk++) s += ti3[i][kk] * st[kk];
        o2[i] = s - tt[i];
    }
    for (int i = 0; i < 3; i++) {
        float s = 0.f;
        for (int kk = 0; kk < 3; kk++) s += k3[i][kk] * o2[kk];
        tv[i] = s;
    }
    float* P = g_params[t];
    P[0] = Mm[0][0]; P[1] = Mm[0][1]; P[2] = Mm[0][2];
    P[3] = Mm[1][0]; P[4] = Mm[1][1]; P[5] = Mm[1][2];
    P[6] = Mm[2][0]; P[7] = Mm[2][1]; P[8] = Mm[2][2];
    P[9] = tv[0]; P[10] = tv[1]; P[11] = tv[2];
    P[12] = k3[0][0]; P[13] = k3[1][1]; P[14] = k3[0][2]; P[15] = k3[1][2];
}

// =========================================================================
// epipolar rows
// =========================================================================
__global__ void epipolar_kernel(float* __restrict__ ep) {
    int i = blockIdx.x, b = blockIdx.y, dir = blockIdx.z;
    const float* P = g_params[dir * 4 + b];
    float M0 = P[0], M1 = P[1], M2 = P[2], M3 = P[3], M4 = P[4], M5 = P[5],
          M6 = P[6], M7 = P[7], M8 = P[8];
    float tv0 = P[9], tv1 = P[10], tv2 = P[11];
    float fx = P[12], fy = P[13], cx = P[14], cy = P[15];

    float ncx = ((float)(i & 31) - cx) / fx;
    float ncy = ((float)(i >> 5) - cy) / fy;
    float pux = M0 * ncx + M1 * ncy + M2 + tv0;
    float puy = M3 * ncx + M4 * ncy + M5 + tv1;
    float puz = M6 * ncx + M7 * ncy + M8 + tv2;
    float invz = 1.0f / (puz + 1e-6f);
    float px = pux * invz, py = puy * invz, pz = puz * invz;
    float ozi = 1.0f / tv2;
    float ox = tv0 * ozi, oy = tv1 * ozi, oz = tv2 * ozi;
    float ax = px - ox, ay = py - oy, az = pz - oz;
    float vlen = sqrtf(ax * ax + ay * ay + az * az);

    int tid = threadIdx.x;
    float dwv[4];
    float lmax = -1e30f;
#pragma unroll
    for (int it = 0; it < 4; it++) {
        int j = tid + it * 256;
        float bx = (float)(j & 31) - ox;
        float by = (float)(j >> 5) - oy;
        float bz = 1.0f - oz;
        float crx = ay * bz - az * by;
        float cry = az * bx - ax * bz;
        float crz = ax * by - ay * bx;
        float area = sqrtf(crx * crx + cry * cry + crz * crz);
        float dist = area / vlen;
        float dw = 1.0f / (1.0f + expf(50.0f * (dist - 0.5f)));
        dwv[it] = dw;
        lmax = fmaxf(lmax, dw);
    }
    __shared__ float red[256];
    red[tid] = lmax;
    __syncthreads();
    for (int s = 128; s > 0; s >>= 1) {
        if (tid < s) red[tid] = fmaxf(red[tid], red[tid + s]);
        __syncthreads();
    }
    float rmax = red[0];
    float* dst = ep + ((size_t)((dir * 4 + b) * 1024 + i) << 10);
#pragma unroll
    for (int it = 0; it < 4; it++) {
        int j = tid + it * 256;
        dst[j] = (rmax < 0.5f) ? 1.0f : dwv[it];
    }
}

// =========================================================================
// wmap = e1 * e2^T, plus 12-way head broadcast to output
// =========================================================================
__global__ void wmap_kernel(const float* __restrict__ ep,
                            float* __restrict__ wm,
                            float* __restrict__ out_wm) {
    int b = blockIdx.z;
    int I0 = blockIdx.y << 5, J0 = blockIdx.x << 5;
    int tx = threadIdx.x, ty = threadIdx.y;
    __shared__ float s1[32][33];
    const float* e0 = ep + ((size_t)(b * 1024) << 10);
    const float* e1 = ep + ((size_t)((4 + b) * 1024) << 10);
    float a = e0[(size_t)(I0 + ty) * 1024 + J0 + tx];
    s1[ty][tx] = e1[(size_t)(J0 + ty) * 1024 + I0 + tx];
    __syncthreads();
    float w = a * s1[tx][ty];
    size_t off = (size_t)(I0 + ty) * 1024 + J0 + tx;
    wm[((size_t)b << 20) + off] = w;
#pragma unroll
    for (int h = 0; h < 12; h++)
        out_wm[((size_t)(b * 12 + h) << 20) + off] = w;
}

// =========================================================================
// layernorm: one warp per row, shuffle-only reductions
// =========================================================================
__global__ void ln_kernel(const float* __restrict__ in, const float* __restrict__ res,
                          const float* __restrict__ gam, const float* __restrict__ bet,
                          float* __restrict__ out) {
    int row = (blockIdx.x << 3) + (threadIdx.x >> 5);
    int lane = threadIdx.x & 31;
    const float* p = in + (size_t)row * 768;
    float v[24];
    float s = 0.f;
#pragma unroll
    for (int it = 0; it < 24; it++) {
        int c = lane + (it << 5);
        v[it] = p[c];
        if (res) v[it] += res[(size_t)row * 768 + c];
        s += v[it];
    }
#pragma unroll
    for (int o = 16; o > 0; o >>= 1) s += __shfl_xor_sync(0xffffffffu, s, o);
    float mu = s * (1.0f / 768.0f);
    float qsum = 0.f;
#pragma unroll
    for (int it = 0; it < 24; it++) {
        float d = v[it] - mu;
        qsum += d * d;
    }
#pragma unroll
    for (int o = 16; o > 0; o >>= 1) qsum += __shfl_xor_sync(0xffffffffu, qsum, o);
    float rstd = rsqrtf(qsum * (1.0f / 768.0f) + 1e-5f);
#pragma unroll
    for (int it = 0; it < 24; it++) {
        int c = lane + (it << 5);
        out[(size_t)row * 768 + c] = (v[it] - mu) * rstd * gam[c] + bet[c];
    }
}

// =========================================================================
// launch
// =========================================================================
extern "C" void kernel_launch(void* const* d_in, const int* in_sizes, int n_in,
                              void* d_out, int out_size) {
    const float* x      = (const float*)d_in[0];
    const float* src    = (const float*)d_in[1];
    const float* intr   = (const float*)d_in[2];
    const float* c2w    = (const float*)d_in[3];
    const float* lnq_g  = (const float*)d_in[4];
    const float* lnq_b  = (const float*)d_in[5];
    const float* Wq     = (const float*)d_in[6];
    const float* bq     = (const float*)d_in[7];
    const float* lnk_g  = (const float*)d_in[8];
    const float* lnk_b  = (const float*)d_in[9];
    const float* Wk     = (const float*)d_in[10];
    const float* bk     = (const float*)d_in[11];
    const float* lnv_g  = (const float*)d_in[12];
    const float* lnv_b  = (const float*)d_in[13];
    const float* Wv     = (const float*)d_in[14];
    const float* bv     = (const float*)d_in[15];
    const float* Wp     = (const float*)d_in[16];
    const float* bp     = (const float*)d_in[17];
    const float* pre_g  = (const float*)d_in[18];
    const float* pre_b  = (const float*)d_in[19];
    const float* W1     = (const float*)d_in[20];
    const float* b1     = (const float*)d_in[21];
    const float* W2     = (const float*)d_in[22];
    const float* b2     = (const float*)d_in[23];
    const float* post_g = (const float*)d_in[24];
    const float* post_b = (const float*)d_in[25];

    float* out_z  = (float*)d_out;
    float* out_wm = out_z + (size_t)4 * 1024 * 768;

    void* sp = nullptr;
    cudaGetSymbolAddress(&sp, g_scratch);
    float* base = (float*)sp;
    float* ep  = base + OFF_EP;
    float* wm  = base + OFF_WM;
    float* lnx = base + OFF_LNX;
    float* lnk = base + OFF_LNK;
    float* lnv = base + OFF_LNV;
    float* qb  = base + OFF_Q;
    float* kb  = base + OFF_K;
    float* vb  = base + OFF_V;
    float* att = base + OFF_ATT;
    float* p0  = base + OFF_P0;
    float* z0  = base + OFF_Z0;
    float* hid = base + OFF_HID;
    float* wqt = base + OFF_WQT;
    float* wkt = base + OFF_WKT;
    float* wvt = base + OFF_WVT;
    float* wpt = base + OFF_WPT;
    float* w1t = base + OFF_W1T;
    float* w2t = base + OFF_W2T;

    static int attn_smem_set = 0;
    if (!attn_smem_set) {
        cudaFuncSetAttribute(attn_mma_kernel,
                             cudaFuncAttributeMaxDynamicSharedMemorySize, 138240);
        attn_smem_set = 1;
    }

    dim3 tb(32, 32);
    transpose_kernel<<<dim3(24, 24), tb>>>(Wq, wqt, 768, 768);
    transpose_kernel<<<dim3(24, 24), tb>>>(Wk, wkt, 768, 768);
    transpose_kernel<<<dim3(24, 24), tb>>>(Wv, wvt, 768, 768);
    transpose_kernel<<<dim3(24, 24), tb>>>(Wp, wpt, 768, 768);
    transpose_kernel<<<dim3(48, 24), tb>>>(W1, w1t, 768, 1536);
    transpose_kernel<<<dim3(24, 48), tb>>>(W2, w2t, 1536, 768);

    setup_params_kernel<<<1, 8>>>(intr, c2w);
    epipolar_kernel<<<dim3(1024, 4, 2), 256>>>(ep);
    wmap_kernel<<<dim3(32, 32, 4), dim3(32, 32)>>>(ep, wm, out_wm);

    ln_kernel<<<512, 256>>>(x, nullptr, lnq_g, lnq_b, lnx);
    ln_kernel<<<512, 256>>>(src, nullptr, lnk_g, lnk_b, lnk);
    ln_kernel<<<512, 256>>>(src, nullptr, lnv_g, lnv_b, lnv);

    gemm_mma_kernel<<<dim3(6, 32), 256>>>(lnx, wqt, bq, qb, 4096, 768, 768, 0);
    gemm_mma_kernel<<<dim3(6, 32), 256>>>(lnk, wkt, bk, kb, 4096, 768, 768, 0);
    gemm_mma_kernel<<<dim3(6, 32), 256>>>(lnv, wvt, bv, vb, 4096, 768, 768, 0);

    attn_mma_kernel<<<dim3(8, 48), 256, 138240>>>(qb, kb, vb, wm, att);

    gemm_mma_kernel<<<dim3(6, 32), 256>>>(att, wpt, bp, p0, 4096, 768, 768, 0);
    ln_kernel<<<512, 256>>>(p0, nullptr, pre_g, pre_b, z0);
    gemm_mma_kernel<<<dim3(12, 32), 256>>>(z0, w1t, b1, hid, 4096, 1536, 768, 1);
    gemm_mma_kernel<<<dim3(6, 32), 256>>>(hid, w2t, b2, p0, 4096, 768, 1536, 0);
    ln_kernel<<<512, 256>>>(p0, z0, post_g, post_b, out_z);
}